// round 14
// baseline (speedup 1.0000x reference)
#include <cuda_runtime.h>
#include <cuda_fp16.h>

// Problem constants
#define FX 80
#define NX 128
#define HH 512
#define WW 1024
#define BC 16                 // B*C fused channel count
#define M  (FX * NX * NX)     // 1310720 texels per channel
#define HW (HH * WW)          // 524288 pixels

// Scratch: x transposed + converted to fp16, layout [M][16] halfs (32B/texel).
__device__ __align__(128) __half g_xt[(size_t)M * BC];

__device__ __forceinline__ unsigned int h2u(__half2 h) {
    return *reinterpret_cast<unsigned int*>(&h);
}

// ---------------------------------------------------------------------------
// Pass 1: fused transpose+convert, register-only scalar (measured floor
// ~17.1us). __ldlu keeps the dead 80MB read stream out of L2 so the dirty
// table survives until the sample pass (measured -2.3us vs no hint).
// ---------------------------------------------------------------------------
__global__ void __launch_bounds__(256) transpose_kernel(const float* __restrict__ x) {
    const int m = blockIdx.x * 256 + threadIdx.x;   // one texel per thread

    float v[16];
#pragma unroll
    for (int c = 0; c < 16; c++)
        v[c] = __ldlu(x + (size_t)c * M + m);       // 16 coalesced last-use LDG.32

    unsigned int w[8];
#pragma unroll
    for (int j = 0; j < 8; j++)
        w[j] = h2u(__floats2half2_rn(v[2 * j], v[2 * j + 1]));

    uint4* dst = reinterpret_cast<uint4*>(g_xt + (size_t)m * BC);
    dst[0] = make_uint4(w[0], w[1], w[2], w[3]);
    dst[1] = make_uint4(w[4], w[5], w[6], w[7]);
}

// accumulate 8 fp16 channels (one uint4) into fp32 accumulators with weight w
__device__ __forceinline__ void acc8(float* r, const uint4& a, float w) {
    const __half2* h = reinterpret_cast<const __half2*>(&a);
#pragma unroll
    for (int j = 0; j < 4; j++) {
        float2 f = __half22float2(h[j]);
        r[2 * j]     = fmaf(f.x, w, r[2 * j]);
        r[2 * j + 1] = fmaf(f.y, w, r[2 * j + 1]);
    }
}

// ---------------------------------------------------------------------------
// Pass 2: bilinear gather — 1 thread per WHOLE pixel (16 channels), no smem.
// uv load + index + weight math computed ONCE per pixel (was duplicated 2x
// in the 18.1us variant); 8 independent LDG.128 per thread (MLP=8); 16
// direct STG.32 finals, warp = 32 consecutive pixels -> 128B-coalesced per
// channel plane. Cross-round data: per-thread gather work is strongly
// sublinear in cost (R7: 4 LDG.128/thread @ 524K threads = 14.6us), so
// doubling payload per thread while halving thread count should win.
// ---------------------------------------------------------------------------
__global__ void __launch_bounds__(256) sample_kernel(const int*   __restrict__ quad,
                                                     const float* __restrict__ uv,
                                                     float*       __restrict__ out) {
    const int pix = blockIdx.x * 256 + threadIdx.x;

    const float2 uvp = reinterpret_cast<const float2*>(uv)[pix];
    const int    f   = quad[pix];

    int u0 = min(max((int)floorf(uvp.x), 0), NX - 2);
    int v0 = min(max((int)floorf(uvp.y), 0), NX - 2);
    const float du = uvp.x - (float)u0;
    const float dv = uvp.y - (float)v0;

    const __half* base = g_xt + ((size_t)((f * NX + v0) * NX + u0)) * BC;

    // 8 independent LDG.128: 2 per corner (16 channels = 32B each corner)
    const uint4 a00lo = *reinterpret_cast<const uint4*>(base);
    const uint4 a00hi = *reinterpret_cast<const uint4*>(base + 8);
    const uint4 a01lo = *reinterpret_cast<const uint4*>(base + BC);
    const uint4 a01hi = *reinterpret_cast<const uint4*>(base + BC + 8);
    const uint4 a10lo = *reinterpret_cast<const uint4*>(base + BC * NX);
    const uint4 a10hi = *reinterpret_cast<const uint4*>(base + BC * NX + 8);
    const uint4 a11lo = *reinterpret_cast<const uint4*>(base + BC * NX + BC);
    const uint4 a11hi = *reinterpret_cast<const uint4*>(base + BC * NX + BC + 8);

    const float w00 = (1.0f - du) * (1.0f - dv);
    const float w01 = du * (1.0f - dv);
    const float w10 = (1.0f - du) * dv;
    const float w11 = du * dv;

    float rlo[8], rhi[8];
#pragma unroll
    for (int j = 0; j < 8; j++) { rlo[j] = 0.0f; rhi[j] = 0.0f; }
    acc8(rlo, a00lo, w00);  acc8(rhi, a00hi, w00);
    acc8(rlo, a01lo, w01);  acc8(rhi, a01hi, w01);
    acc8(rlo, a10lo, w10);  acc8(rhi, a10hi, w10);
    acc8(rlo, a11lo, w11);  acc8(rhi, a11hi, w11);

    // direct stores: warp covers 32 consecutive pixels -> 128B per plane
    float* o = out + pix;
#pragma unroll
    for (int k = 0; k < 8; k++)
        o[(size_t)k * HW] = rlo[k];
#pragma unroll
    for (int k = 0; k < 8; k++)
        o[(size_t)(k + 8) * HW] = rhi[k];
}

extern "C" void kernel_launch(void* const* d_in, const int* in_sizes, int n_in,
                              void* d_out, int out_size) {
    const float* x    = (const float*)d_in[0];   // [2,8,80,128,128] fp32
    const int*   quad = (const int*)  d_in[1];   // [512,1024] int32
    const float* uv   = (const float*)d_in[2];   // [512,1024,2] fp32
    float*       out  = (float*)d_out;           // [2,8,512,1024] fp32

    transpose_kernel<<<M / 256, 256>>>(x);            // 5120 blocks
    sample_kernel<<<HW / 256, 256>>>(quad, uv, out);  // 2048 blocks
}

// round 15
// speedup vs baseline: 1.0513x; 1.0513x over previous
#include <cuda_runtime.h>
#include <cuda_fp16.h>

// Problem constants
#define FX 80
#define NX 128
#define HH 512
#define WW 1024
#define BC 16                 // B*C fused channel count
#define M  (FX * NX * NX)     // 1310720 texels per channel
#define HW (HH * WW)          // 524288 pixels

// Scratch: x transposed + converted to fp16, layout [M][16] halfs (32B/texel).
__device__ __align__(128) __half g_xt[(size_t)M * BC];

__device__ __forceinline__ unsigned int h2u(__half2 h) {
    return *reinterpret_cast<unsigned int*>(&h);
}

// ---------------------------------------------------------------------------
// Pass 1: fused transpose+convert, register-only scalar (measured floor
// ~17.1us). __ldlu keeps the dead 80MB read stream out of L2 so the dirty
// table survives until the sample pass (measured -2.3us vs no hint).
// UNCHANGED from the 35.3us best.
// ---------------------------------------------------------------------------
__global__ void __launch_bounds__(256) transpose_kernel(const float* __restrict__ x) {
    const int m = blockIdx.x * 256 + threadIdx.x;   // one texel per thread

    float v[16];
#pragma unroll
    for (int c = 0; c < 16; c++)
        v[c] = __ldlu(x + (size_t)c * M + m);       // 16 coalesced last-use LDG.32

    unsigned int w[8];
#pragma unroll
    for (int j = 0; j < 8; j++)
        w[j] = h2u(__floats2half2_rn(v[2 * j], v[2 * j + 1]));

    uint4* dst = reinterpret_cast<uint4*>(g_xt + (size_t)m * BC);
    dst[0] = make_uint4(w[0], w[1], w[2], w[3]);
    dst[1] = make_uint4(w[4], w[5], w[6], w[7]);
}

// accumulate 8 fp16 channels (one uint4) into fp32 accumulators with weight w
__device__ __forceinline__ void acc8(float* r, const uint4& a, float w) {
    const __half2* h = reinterpret_cast<const __half2*>(&a);
#pragma unroll
    for (int j = 0; j < 4; j++) {
        float2 f = __half22float2(h[j]);
        r[2 * j]     = fmaf(f.x, w, r[2 * j]);
        r[2 * j + 1] = fmaf(f.y, w, r[2 * j + 1]);
    }
}

// ---------------------------------------------------------------------------
// Pass 2: bilinear gather — the measured-floor R4/R9 shape (2 thr/pixel,
// 4 x LDG.128, direct stores), two micro-tunes:
//  - output stores via __stwt: write-once data bypasses L2 allocation so
//    the 40MB table keeps its L2 residency during the gather phase
//  - block 128 (8192 blocks): finer wave granularity -> smaller tail
// ---------------------------------------------------------------------------
__global__ void __launch_bounds__(128) sample_kernel(const int*   __restrict__ quad,
                                                     const float* __restrict__ uv,
                                                     float*       __restrict__ out) {
    const int t   = threadIdx.x;
    const int p   = t >> 1;            // pixel-in-tile 0..63
    const int hg  = t & 1;             // half-group: channels hg*8 .. hg*8+7
    const int pix = blockIdx.x * 64 + p;

    const float2 uvp = reinterpret_cast<const float2*>(uv)[pix];
    const int    f   = quad[pix];

    int u0 = min(max((int)floorf(uvp.x), 0), NX - 2);
    int v0 = min(max((int)floorf(uvp.y), 0), NX - 2);
    const float du = uvp.x - (float)u0;
    const float dv = uvp.y - (float)v0;

    const __half* base = g_xt + ((size_t)((f * NX + v0) * NX + u0)) * BC + hg * 8;
    const uint4 a00 = *reinterpret_cast<const uint4*>(base);
    const uint4 a01 = *reinterpret_cast<const uint4*>(base + BC);
    const uint4 a10 = *reinterpret_cast<const uint4*>(base + BC * NX);
    const uint4 a11 = *reinterpret_cast<const uint4*>(base + BC * NX + BC);

    const float w00 = (1.0f - du) * (1.0f - dv);
    const float w01 = du * (1.0f - dv);
    const float w10 = (1.0f - du) * dv;
    const float w11 = du * dv;

    float r[8];
#pragma unroll
    for (int j = 0; j < 8; j++) r[j] = 0.0f;
    acc8(r, a00, w00);
    acc8(r, a01, w01);
    acc8(r, a10, w10);
    acc8(r, a11, w11);

    // direct coalesced stores, write-through (no L2 allocation for out)
    float* o = out + (size_t)(hg * 8) * HW + pix;
#pragma unroll
    for (int k = 0; k < 8; k++)
        __stwt(o + (size_t)k * HW, r[k]);
}

extern "C" void kernel_launch(void* const* d_in, const int* in_sizes, int n_in,
                              void* d_out, int out_size) {
    const float* x    = (const float*)d_in[0];   // [2,8,80,128,128] fp32
    const int*   quad = (const int*)  d_in[1];   // [512,1024] int32
    const float* uv   = (const float*)d_in[2];   // [512,1024,2] fp32
    float*       out  = (float*)d_out;           // [2,8,512,1024] fp32

    transpose_kernel<<<M / 256, 256>>>(x);           // 5120 blocks
    sample_kernel<<<HW / 64, 128>>>(quad, uv, out);  // 8192 blocks
}

// round 16
// speedup vs baseline: 1.0589x; 1.0073x over previous
#include <cuda_runtime.h>
#include <cuda_fp16.h>

// Problem constants
#define FX 80
#define NX 128
#define HH 512
#define WW 1024
#define BC 16                 // B*C fused channel count
#define M  (FX * NX * NX)     // 1310720 texels per channel
#define HW (HH * WW)          // 524288 pixels

// Scratch: x transposed + converted to fp16, layout [M][16] halfs (32B/texel).
__device__ __align__(128) __half g_xt[(size_t)M * BC];

__device__ __forceinline__ unsigned int h2u(__half2 h) {
    return *reinterpret_cast<unsigned int*>(&h);
}

// ---------------------------------------------------------------------------
// Pass 1: fused transpose+convert, register-only scalar (measured floor
// ~17.1us = 120MB at the DRAM roof incl. structural write-back).
// __ldlu keeps the dead 80MB read stream out of L2 so the dirty table
// survives until the sample pass (measured -2.3us vs no hint).
// ---------------------------------------------------------------------------
__global__ void __launch_bounds__(256) transpose_kernel(const float* __restrict__ x) {
    const int m = blockIdx.x * 256 + threadIdx.x;   // one texel per thread

    float v[16];
#pragma unroll
    for (int c = 0; c < 16; c++)
        v[c] = __ldlu(x + (size_t)c * M + m);       // 16 coalesced last-use LDG.32

    unsigned int w[8];
#pragma unroll
    for (int j = 0; j < 8; j++)
        w[j] = h2u(__floats2half2_rn(v[2 * j], v[2 * j + 1]));

    uint4* dst = reinterpret_cast<uint4*>(g_xt + (size_t)m * BC);
    dst[0] = make_uint4(w[0], w[1], w[2], w[3]);
    dst[1] = make_uint4(w[4], w[5], w[6], w[7]);
}

// accumulate 8 fp16 channels (one uint4) into fp32 accumulators with weight w
__device__ __forceinline__ void acc8(float* r, const uint4& a, float w) {
    const __half2* h = reinterpret_cast<const __half2*>(&a);
#pragma unroll
    for (int j = 0; j < 4; j++) {
        float2 f = __half22float2(h[j]);
        r[2 * j]     = fmaf(f.x, w, r[2 * j]);
        r[2 * j + 1] = fmaf(f.y, w, r[2 * j + 1]);
    }
}

// load one 16B corner chunk with .cg (L2-only, skip L1 allocation):
// random 32B gathers have ~zero L1 hit rate, so L1 fill is pure overhead.
__device__ __forceinline__ uint4 ldcg16(const __half* p) {
    return __ldcg(reinterpret_cast<const uint4*>(p));
}

// ---------------------------------------------------------------------------
// Pass 2: bilinear gather — R11-exact shape (measured best: 2 thr/pixel,
// 4 x LDG.128, direct scalar stores, block 256), one change: table gathers
// use __ldcg to bypass L1 allocation (no reuse there, 4x fill amplification).
// ---------------------------------------------------------------------------
__global__ void __launch_bounds__(256) sample_kernel(const int*   __restrict__ quad,
                                                     const float* __restrict__ uv,
                                                     float*       __restrict__ out) {
    const int t   = threadIdx.x;
    const int p   = t >> 1;            // pixel-in-tile 0..127
    const int hg  = t & 1;             // half-group: channels hg*8 .. hg*8+7
    const int pix = blockIdx.x * 128 + p;

    const float2 uvp = reinterpret_cast<const float2*>(uv)[pix];
    const int    f   = quad[pix];

    int u0 = min(max((int)floorf(uvp.x), 0), NX - 2);
    int v0 = min(max((int)floorf(uvp.y), 0), NX - 2);
    const float du = uvp.x - (float)u0;
    const float dv = uvp.y - (float)v0;

    const __half* base = g_xt + ((size_t)((f * NX + v0) * NX + u0)) * BC + hg * 8;
    const uint4 a00 = ldcg16(base);
    const uint4 a01 = ldcg16(base + BC);
    const uint4 a10 = ldcg16(base + BC * NX);
    const uint4 a11 = ldcg16(base + BC * NX + BC);

    const float w00 = (1.0f - du) * (1.0f - dv);
    const float w01 = du * (1.0f - dv);
    const float w10 = (1.0f - du) * dv;
    const float w11 = du * dv;

    float r[8];
#pragma unroll
    for (int j = 0; j < 8; j++) r[j] = 0.0f;
    acc8(r, a00, w00);
    acc8(r, a01, w01);
    acc8(r, a10, w10);
    acc8(r, a11, w11);

    // direct coalesced stores: 16 lanes of same hg -> 16 consecutive pixels
    float* o = out + (size_t)(hg * 8) * HW + pix;
#pragma unroll
    for (int k = 0; k < 8; k++)
        o[(size_t)k * HW] = r[k];
}

extern "C" void kernel_launch(void* const* d_in, const int* in_sizes, int n_in,
                              void* d_out, int out_size) {
    const float* x    = (const float*)d_in[0];   // [2,8,80,128,128] fp32
    const int*   quad = (const int*)  d_in[1];   // [512,1024] int32
    const float* uv   = (const float*)d_in[2];   // [512,1024,2] fp32
    float*       out  = (float*)d_out;           // [2,8,512,1024] fp32

    transpose_kernel<<<M / 256, 256>>>(x);            // 5120 blocks
    sample_kernel<<<HW / 128, 256>>>(quad, uv, out);  // 4096 blocks
}